// round 12
// baseline (speedup 1.0000x reference)
#include <cuda_runtime.h>
#include <cuda_fp16.h>

// Operator3D: bs=4, v=8192, n=20, SUPPORT=4, KERNEL=32  (S*K = 128)
// fp16 inner loop: supports packed pairwise into half2 -> per row-neighbor
// 6 HFMA2-class + 2 HMAX2 instead of 12 FFMA + 4 FMNMX (same rt class, 2x
// work per slot, normal 32-bit operands -- unlike the failed f32x2 path).
// Gather/convert, weight scale and final sum remain fp32. Shell = R9 (best):
// warp-per-2-rows, batched gather, idx prefetch, 740 blocks.

#define BS_   4
#define V_    8192
#define N_    20
#define K_    32
#define SK_   128
#define ROWS_ (BS_ * V_)

#define GR_      2
#define GITEMS_  (GR_ * N_)            // 40
#define GROUPS_  (ROWS_ / GR_)         // 16384

#define WPB      8
#define THREADS_ (WPB * 32)
#define BLOCKS_  740
#define NWARPS_  (BLOCKS_ * WPB)       // 5920

typedef unsigned int u32;

__device__ __forceinline__ u32 packh2(float a, float b) {   // {low=a, high=b}
    u32 r;
    asm("cvt.rn.f16x2.f32 %0, %1, %2;" : "=r"(r) : "f"(b), "f"(a));
    return r;
}
__device__ __forceinline__ __half2 u2h(u32 v) {
    return *reinterpret_cast<__half2*>(&v);
}

__global__ __launch_bounds__(THREADS_, 5)
void op3d_kernel(const int*   __restrict__ nb,
                 const float* __restrict__ verts,
                 const float* __restrict__ weights,
                 const float* __restrict__ disp,
                 float*       __restrict__ out)
{
    // per item: {x2,y2,z2,pad} half2-packed -> one LDS.128 per row per j
    __shared__ uint4 sd[WPB][GITEMS_];

    const int warp  = threadIdx.x >> 5;
    const int lane  = threadIdx.x & 31;
    const int gwarp = blockIdx.x * WPB + warp;

    // Support-paired displacement columns in half2: low=s0/s2, high=s1/s3.
    const __half2 D0_01 = u2h(packh2(disp[0*SK_ +  0 + lane], disp[0*SK_ + 32 + lane]));
    const __half2 D0_23 = u2h(packh2(disp[0*SK_ + 64 + lane], disp[0*SK_ + 96 + lane]));
    const __half2 D1_01 = u2h(packh2(disp[1*SK_ +  0 + lane], disp[1*SK_ + 32 + lane]));
    const __half2 D1_23 = u2h(packh2(disp[1*SK_ + 64 + lane], disp[1*SK_ + 96 + lane]));
    const __half2 D2_01 = u2h(packh2(disp[2*SK_ +  0 + lane], disp[2*SK_ + 32 + lane]));
    const __half2 D2_23 = u2h(packh2(disp[2*SK_ + 64 + lane], disp[2*SK_ + 96 + lane]));
    const float w0 = weights[ 0 + lane];
    const float w1 = weights[32 + lane];
    const float w2 = weights[64 + lane];
    const float w3 = weights[96 + lane];

    const bool hasExtra = (lane < GITEMS_ - 32);   // lanes 0..7

    int g = gwarp;

    int i0 = 0, i1 = 0;
    if (g < GROUPS_) {
        const int gb = g * GITEMS_;
        i0 = nb[gb + lane];
        if (hasExtra) i1 = nb[gb + 32 + lane];
    }

    while (g < GROUPS_) {
        const int r0    = g * GR_;
        const int vbase = (r0 >> 13) * (V_ * 3);

        // 1) prefetch next group's indices
        const int gn = g + NWARPS_;
        int n0 = 0, n1 = 0;
        if (gn < GROUPS_) {
            const int gbn = gn * GITEMS_;
            n0 = nb[gbn + lane];
            if (hasExtra) n1 = nb[gbn + 32 + lane];
        }

        // 2) batched gather; convert to duplicated half2 off the hot path
        {
            const int   row0 = (lane >= N_);
            const float* p0  = verts + vbase + i0 * 3;
            const float* q0  = verts + (r0 + row0) * 3;
            float dx = p0[0]-q0[0], dy = p0[1]-q0[1], dz = p0[2]-q0[2];
            sd[warp][lane] = make_uint4(packh2(dx,dx), packh2(dy,dy),
                                        packh2(dz,dz), 0u);
            if (hasExtra) {
                const float* p1 = verts + vbase + i1 * 3;
                const float* q1 = verts + (r0 + 1) * 3;
                float ex = p1[0]-q1[0], ey = p1[1]-q1[1], ez = p1[2]-q1[2];
                sd[warp][lane + 32] = make_uint4(packh2(ex,ex), packh2(ey,ey),
                                                 packh2(ez,ez), 0u);
            }
        }
        __syncwarp();

        // 3) fused 2-row fp16 compute: 4 half2 max-chains (8 scalar chains),
        //    2 LDS.128 + 12 HFMA2-class + 4 HMAX2 per j. max seeded 0 = relu.
        __half2 A01 = __float2half2_rn(0.0f), A23 = __float2half2_rn(0.0f);
        __half2 B01 = __float2half2_rn(0.0f), B23 = __float2half2_rn(0.0f);
        {
            const uint4* s0 = &sd[warp][0];
            const uint4* s1 = &sd[warp][N_];
            #pragma unroll
            for (int j = 0; j < N_; j++) {
                const uint4 A = s0[j];
                const uint4 B = s1[j];
                const __half2 ax = u2h(A.x), ay = u2h(A.y), az = u2h(A.z);
                const __half2 bx = u2h(B.x), by = u2h(B.y), bz = u2h(B.z);

                __half2 ta01 = __hfma2(ax, D0_01, __hfma2(ay, D1_01, __hmul2(az, D2_01)));
                __half2 tb01 = __hfma2(bx, D0_01, __hfma2(by, D1_01, __hmul2(bz, D2_01)));
                __half2 ta23 = __hfma2(ax, D0_23, __hfma2(ay, D1_23, __hmul2(az, D2_23)));
                __half2 tb23 = __hfma2(bx, D0_23, __hfma2(by, D1_23, __hmul2(bz, D2_23)));

                A01 = __hmax2(A01, ta01);
                B01 = __hmax2(B01, tb01);
                A23 = __hmax2(A23, ta23);
                B23 = __hmax2(B23, tb23);
            }
        }

        // 4) fp32 epilogue: unpack maxes, scale by weights, sum supports
        {
            float m0 = __low2float(A01), m1 = __high2float(A01);
            float m2 = __low2float(A23), m3 = __high2float(A23);
            out[r0 * K_ + lane] =
                fmaf(m0, w0, fmaf(m1, w1, fmaf(m2, w2, m3 * w3)));
            float p0 = __low2float(B01), p1 = __high2float(B01);
            float p2 = __low2float(B23), p3 = __high2float(B23);
            out[(r0 + 1) * K_ + lane] =
                fmaf(p0, w0, fmaf(p1, w1, fmaf(p2, w2, p3 * w3)));
        }

        g  = gn;
        i0 = n0;
        i1 = n1;
        __syncwarp();
    }
}

extern "C" void kernel_launch(void* const* d_in, const int* in_sizes, int n_in,
                              void* d_out, int out_size)
{
    const int*   nb      = (const int*)  d_in[0];
    const float* verts   = (const float*)d_in[1];
    const float* weights = (const float*)d_in[2];
    const float* disp    = (const float*)d_in[3];
    float*       out     = (float*)      d_out;

    op3d_kernel<<<BLOCKS_, THREADS_>>>(nb, verts, weights, disp, out);
}

// round 13
// speedup vs baseline: 1.1732x; 1.1732x over previous
#include <cuda_runtime.h>

// Operator3D: bs=4, v=8192, n=20, SUPPORT=4, KERNEL=32  (S*K = 128)
// inputs: [0] neighbor_index int32 (bs,v,n)
//         [1] vertices       f32   (bs,v,3)
//         [2] weights        f32   (1,1,4,32)
//         [3] displacement   f32   (3,128)
// output: feature f32 (bs,v,32)
//
// R9 fused fp32 scalar body (best measured) + 2-deep gather pipeline:
//   indices  prefetched 2 groups ahead,
//   vertex displacements prefetched 1 group ahead.
// The next-group LDGs are issued right after the syncwarp; their consumers
// (FSUB -> STS) sit at the TOP OF THE NEXT ITERATION, i.e. behind ~680
// compute slots, so the verts-gather latency (the last ~29% of issue slots)
// is never exposed. All vector-math paths (f32x2, f16x2) are abandoned:
// 4/4 regressions, scalar FFMA/FMNMX is optimal on this chip.

#define BS_   4
#define V_    8192
#define N_    20
#define K_    32
#define SK_   128
#define ROWS_ (BS_ * V_)

#define GR_      2
#define GITEMS_  (GR_ * N_)            // 40
#define GROUPS_  (ROWS_ / GR_)         // 16384

#define WPB      8
#define THREADS_ (WPB * 32)
#define BLOCKS_  740                   // best measured geometry (R9)
#define NWARPS_  (BLOCKS_ * WPB)       // 5920

__global__ __launch_bounds__(THREADS_, 4)
void op3d_kernel(const int*   __restrict__ nb,
                 const float* __restrict__ verts,
                 const float* __restrict__ weights,
                 const float* __restrict__ disp,
                 float*       __restrict__ out)
{
    __shared__ float4 sd[WPB][GITEMS_];

    const int warp  = threadIdx.x >> 5;
    const int lane  = threadIdx.x & 31;
    const int gwarp = blockIdx.x * WPB + warp;

    // Per-lane constants: displacement columns for k = s*32 + lane, s=0..3.
    const float d00 = disp[0 * SK_ +  0 + lane];
    const float d01 = disp[0 * SK_ + 32 + lane];
    const float d02 = disp[0 * SK_ + 64 + lane];
    const float d03 = disp[0 * SK_ + 96 + lane];
    const float d10 = disp[1 * SK_ +  0 + lane];
    const float d11 = disp[1 * SK_ + 32 + lane];
    const float d12 = disp[1 * SK_ + 64 + lane];
    const float d13 = disp[1 * SK_ + 96 + lane];
    const float d20 = disp[2 * SK_ +  0 + lane];
    const float d21 = disp[2 * SK_ + 32 + lane];
    const float d22 = disp[2 * SK_ + 64 + lane];
    const float d23 = disp[2 * SK_ + 96 + lane];
    const float w0  = weights[ 0 + lane];
    const float w1  = weights[32 + lane];
    const float w2  = weights[64 + lane];
    const float w3  = weights[96 + lane];

    const bool hasExtra = (lane < GITEMS_ - 32);   // lanes 0..7

    // ---------------- pipeline state ----------------
    int   g = gwarp;
    float c0x=0,c0y=0,c0z=0;        // current group, item = lane
    float c1x=0,c1y=0,c1z=0;        // current group, item = lane+32
    int   j0=0, j1=0;               // NEXT group's indices

    // prologue: group g's indices + displacements, group g+NW's indices
    {
        const int gb = g * GITEMS_;
        const int i0 = nb[gb + lane];
        const int i1 = hasExtra ? nb[gb + 32 + lane] : 0;
        const int r0    = g * GR_;
        const int vbase = (r0 >> 13) * (V_ * 3);
        const int  row0 = (lane >= N_);
        const float* p0 = verts + vbase + i0 * 3;
        const float* q0 = verts + (r0 + row0) * 3;
        c0x = p0[0]-q0[0]; c0y = p0[1]-q0[1]; c0z = p0[2]-q0[2];
        if (hasExtra) {
            const float* p1 = verts + vbase + i1 * 3;
            const float* q1 = verts + (r0 + 1) * 3;
            c1x = p1[0]-q1[0]; c1y = p1[1]-q1[1]; c1z = p1[2]-q1[2];
        }
        const int gn = g + NWARPS_;
        if (gn < GROUPS_) {
            const int gbn = gn * GITEMS_;
            j0 = nb[gbn + lane];
            if (hasExtra) j1 = nb[gbn + 32 + lane];
        }
    }

    while (g < GROUPS_) {
        const int r0 = g * GR_;
        const int gn = g + NWARPS_;

        // 1) stage current displacements (already in regs) into smem
        sd[warp][lane] = make_float4(c0x, c0y, c0z, 0.0f);
        if (hasExtra)
            sd[warp][lane + 32] = make_float4(c1x, c1y, c1z, 0.0f);
        __syncwarp();

        // 2) issue NEXT group's verts LDGs + idx LDGs 2 groups ahead.
        //    Consumers (the FSUBs feeding n0x..) are loop-carried: first use
        //    is next iteration's STS, i.e. behind this iteration's compute.
        float n0x=0,n0y=0,n0z=0, n1x=0,n1y=0,n1z=0;
        int   k0=0, k1=0;
        if (gn < GROUPS_) {
            const int rn     = gn * GR_;
            const int vbasen = (rn >> 13) * (V_ * 3);
            const int  row0n = (lane >= N_);
            const float* p0 = verts + vbasen + j0 * 3;
            const float* q0 = verts + (rn + row0n) * 3;
            n0x = p0[0]-q0[0]; n0y = p0[1]-q0[1]; n0z = p0[2]-q0[2];
            if (hasExtra) {
                const float* p1 = verts + vbasen + j1 * 3;
                const float* q1 = verts + (rn + 1) * 3;
                n1x = p1[0]-q1[0]; n1y = p1[1]-q1[1]; n1z = p1[2]-q1[2];
            }
            const int gnn = gn + NWARPS_;
            if (gnn < GROUPS_) {
                const int gbnn = gnn * GITEMS_;
                k0 = nb[gbnn + lane];
                if (hasExtra) k1 = nb[gbnn + 32 + lane];
            }
        }

        // 3) FUSED compute for both rows: 8 independent max chains,
        //    2 independent LDS.128 per j. max seeded 0 == relu.
        float a0=0.f, a1=0.f, a2=0.f, a3=0.f;     // row 0
        float b0=0.f, b1=0.f, b2=0.f, b3=0.f;     // row 1
        {
            const float4* s0 = &sd[warp][0];
            const float4* s1 = &sd[warp][N_];
            #pragma unroll
            for (int j = 0; j < N_; j++) {
                const float4 da = s0[j];
                const float4 db = s1[j];

                float ta0 = fmaf(da.x, d00, fmaf(da.y, d10, da.z * d20));
                float tb0 = fmaf(db.x, d00, fmaf(db.y, d10, db.z * d20));
                float ta1 = fmaf(da.x, d01, fmaf(da.y, d11, da.z * d21));
                float tb1 = fmaf(db.x, d01, fmaf(db.y, d11, db.z * d21));
                float ta2 = fmaf(da.x, d02, fmaf(da.y, d12, da.z * d22));
                float tb2 = fmaf(db.x, d02, fmaf(db.y, d12, db.z * d22));
                float ta3 = fmaf(da.x, d03, fmaf(da.y, d13, da.z * d23));
                float tb3 = fmaf(db.x, d03, fmaf(db.y, d13, db.z * d23));

                a0 = fmaxf(a0, ta0);  b0 = fmaxf(b0, tb0);
                a1 = fmaxf(a1, ta1);  b1 = fmaxf(b1, tb1);
                a2 = fmaxf(a2, ta2);  b2 = fmaxf(b2, tb2);
                a3 = fmaxf(a3, ta3);  b3 = fmaxf(b3, tb3);
            }
        }

        out[ r0      * K_ + lane] = fmaf(a0, w0, fmaf(a1, w1, fmaf(a2, w2, a3 * w3)));
        out[(r0 + 1) * K_ + lane] = fmaf(b0, w0, fmaf(b1, w1, fmaf(b2, w2, b3 * w3)));

        __syncwarp();   // protect smem before next iteration's STS

        // 4) rotate pipeline
        g   = gn;
        c0x = n0x; c0y = n0y; c0z = n0z;
        c1x = n1x; c1y = n1y; c1z = n1z;
        j0  = k0;  j1  = k1;
    }
}

extern "C" void kernel_launch(void* const* d_in, const int* in_sizes, int n_in,
                              void* d_out, int out_size)
{
    const int*   nb      = (const int*)  d_in[0];
    const float* verts   = (const float*)d_in[1];
    const float* weights = (const float*)d_in[2];
    const float* disp    = (const float*)d_in[3];
    float*       out     = (float*)      d_out;

    op3d_kernel<<<BLOCKS_, THREADS_>>>(nb, verts, weights, disp, out);
}

// round 14
// speedup vs baseline: 1.3159x; 1.1216x over previous
#include <cuda_runtime.h>

// Operator3D: bs=4, v=8192, n=20, SUPPORT=4, KERNEL=32  (S*K = 128)
// inputs: [0] neighbor_index int32 (bs,v,n)
//         [1] vertices       f32   (bs,v,3)
//         [2] weights        f32   (1,1,4,32)
//         [3] displacement   f32   (3,128)
// output: feature f32 (bs,v,32)
//
// ONE-SHOT kernel: each warp handles exactly one group of 2 rows, then exits.
// 2048 blocks x 8 warps = 16384 warps = 16384 groups. No grid-stride loop,
// no prefetch state, one syncwarp. The fused 2-row scalar body is kept
// verbatim (FMA-pipe-bound at issue = 34/48 = 70.8%, measured 70.6-71.1 --
// this is the hardware floor for scalar fp32 on sm_103a; vector paths are
// 4/4 measured regressions). This round targets the bench-vs-ncu gap
// (~1.6us) that the persistent-loop shell costs on the timed replay path.

#define BS_   4
#define V_    8192
#define N_    20
#define K_    32
#define SK_   128
#define ROWS_ (BS_ * V_)

#define GR_      2
#define GITEMS_  (GR_ * N_)            // 40
#define GROUPS_  (ROWS_ / GR_)         // 16384

#define WPB      8
#define THREADS_ (WPB * 32)
#define BLOCKS_  (GROUPS_ / WPB)       // 2048: one group per warp, one shot

__global__ __launch_bounds__(THREADS_)
void op3d_kernel(const int*   __restrict__ nb,
                 const float* __restrict__ verts,
                 const float* __restrict__ weights,
                 const float* __restrict__ disp,
                 float*       __restrict__ out)
{
    __shared__ float4 sd[WPB][GITEMS_];

    const int warp = threadIdx.x >> 5;
    const int lane = threadIdx.x & 31;
    const int g    = blockIdx.x * WPB + warp;      // this warp's group
    const int r0   = g * GR_;

    const bool hasExtra = (lane < GITEMS_ - 32);   // lanes 0..7

    // gather: indices first (coalesced), then dependent vert loads
    const int gb = g * GITEMS_;
    const int i0 = nb[gb + lane];
    const int i1 = hasExtra ? nb[gb + 32 + lane] : 0;

    // Per-lane constants load AFTER idx issue (independent, fills the wait)
    const float d00 = disp[0 * SK_ +  0 + lane];
    const float d01 = disp[0 * SK_ + 32 + lane];
    const float d02 = disp[0 * SK_ + 64 + lane];
    const float d03 = disp[0 * SK_ + 96 + lane];
    const float d10 = disp[1 * SK_ +  0 + lane];
    const float d11 = disp[1 * SK_ + 32 + lane];
    const float d12 = disp[1 * SK_ + 64 + lane];
    const float d13 = disp[1 * SK_ + 96 + lane];
    const float d20 = disp[2 * SK_ +  0 + lane];
    const float d21 = disp[2 * SK_ + 32 + lane];
    const float d22 = disp[2 * SK_ + 64 + lane];
    const float d23 = disp[2 * SK_ + 96 + lane];
    const float w0  = weights[ 0 + lane];
    const float w1  = weights[32 + lane];
    const float w2  = weights[64 + lane];
    const float w3  = weights[96 + lane];

    {
        const int vbase = (r0 >> 13) * (V_ * 3);   // groups never span batches
        const int  row0 = (lane >= N_);            // item = lane
        const float* p0 = verts + vbase + i0 * 3;
        const float* q0 = verts + (r0 + row0) * 3;
        sd[warp][lane] = make_float4(p0[0]-q0[0], p0[1]-q0[1],
                                     p0[2]-q0[2], 0.0f);
        if (hasExtra) {                            // item = lane+32 -> row 1
            const float* p1 = verts + vbase + i1 * 3;
            const float* q1 = verts + (r0 + 1) * 3;
            sd[warp][lane + 32] = make_float4(p1[0]-q1[0], p1[1]-q1[1],
                                              p1[2]-q1[2], 0.0f);
        }
    }
    __syncwarp();

    // fused compute for both rows: 8 independent max chains,
    // 2 independent LDS.128 per j; max seeded 0 == relu(max).
    float a0=0.f, a1=0.f, a2=0.f, a3=0.f;     // row 0
    float b0=0.f, b1=0.f, b2=0.f, b3=0.f;     // row 1
    {
        const float4* s0 = &sd[warp][0];
        const float4* s1 = &sd[warp][N_];
        #pragma unroll
        for (int j = 0; j < N_; j++) {
            const float4 da = s0[j];
            const float4 db = s1[j];

            float ta0 = fmaf(da.x, d00, fmaf(da.y, d10, da.z * d20));
            float tb0 = fmaf(db.x, d00, fmaf(db.y, d10, db.z * d20));
            float ta1 = fmaf(da.x, d01, fmaf(da.y, d11, da.z * d21));
            float tb1 = fmaf(db.x, d01, fmaf(db.y, d11, db.z * d21));
            float ta2 = fmaf(da.x, d02, fmaf(da.y, d12, da.z * d22));
            float tb2 = fmaf(db.x, d02, fmaf(db.y, d12, db.z * d22));
            float ta3 = fmaf(da.x, d03, fmaf(da.y, d13, da.z * d23));
            float tb3 = fmaf(db.x, d03, fmaf(db.y, d13, db.z * d23));

            a0 = fmaxf(a0, ta0);  b0 = fmaxf(b0, tb0);
            a1 = fmaxf(a1, ta1);  b1 = fmaxf(b1, tb1);
            a2 = fmaxf(a2, ta2);  b2 = fmaxf(b2, tb2);
            a3 = fmaxf(a3, ta3);  b3 = fmaxf(b3, tb3);
        }
    }

    out[ r0      * K_ + lane] = fmaf(a0, w0, fmaf(a1, w1, fmaf(a2, w2, a3 * w3)));
    out[(r0 + 1) * K_ + lane] = fmaf(b0, w0, fmaf(b1, w1, fmaf(b2, w2, b3 * w3)));
}

extern "C" void kernel_launch(void* const* d_in, const int* in_sizes, int n_in,
                              void* d_out, int out_size)
{
    const int*   nb      = (const int*)  d_in[0];
    const float* verts   = (const float*)d_in[1];
    const float* weights = (const float*)d_in[2];
    const float* disp    = (const float*)d_in[3];
    float*       out     = (float*)      d_out;

    op3d_kernel<<<BLOCKS_, THREADS_>>>(nb, verts, weights, disp, out);
}

// round 15
// speedup vs baseline: 1.4561x; 1.1065x over previous
#include <cuda_runtime.h>
#include <cuda_fp16.h>

// Operator3D: bs=4, v=8192, n=20, SUPPORT=4, KERNEL=32  (S*K = 128)
// inputs: [0] neighbor_index int32 (bs,v,n)
//         [1] vertices       f32   (bs,v,3)
//         [2] weights        f32   (1,1,4,32)
//         [3] displacement   f32   (3,128)
// output: feature f32 (bs,v,32)
//
// Controlled experiment: R14's proven ONE-SHOT shell (one warp = one 2-row
// group, 2048 blocks, no loop/prefetch state) + fp16 half2 inner loop
// (supports packed pairwise). Per j: 2 LDS.128 + 12 HFMA2-class + 4 HMAX2
// = 18 slots, 24 FMA-pipe cycles vs 34/48 scalar. R12's fp16 regression is
// hypothesized to be its persistent shell (since proven costly in R13/R14),
// not the fp16 pipes -- this isolates that. Gather/convert + weight-scale
// epilogue stay fp32. rel_err expected ~3.7e-4 (measured in R12), < 1e-3.

#define BS_   4
#define V_    8192
#define N_    20
#define K_    32
#define SK_   128
#define ROWS_ (BS_ * V_)

#define GR_      2
#define GITEMS_  (GR_ * N_)            // 40
#define GROUPS_  (ROWS_ / GR_)         // 16384

#define WPB      8
#define THREADS_ (WPB * 32)
#define BLOCKS_  (GROUPS_ / WPB)       // 2048: one group per warp, one shot

typedef unsigned int u32;

__device__ __forceinline__ u32 packh2(float lo, float hi) {  // {low=lo, high=hi}
    u32 r;
    asm("cvt.rn.f16x2.f32 %0, %1, %2;" : "=r"(r) : "f"(hi), "f"(lo));
    return r;
}
__device__ __forceinline__ __half2 u2h(u32 v) {
    __half2 h;
    *reinterpret_cast<u32*>(&h) = v;
    return h;
}

__global__ __launch_bounds__(THREADS_)
void op3d_kernel(const int*   __restrict__ nb,
                 const float* __restrict__ verts,
                 const float* __restrict__ weights,
                 const float* __restrict__ disp,
                 float*       __restrict__ out)
{
    // per item: {(dx,dx),(dy,dy),(dz,dz),pad} as half2 -> one LDS.128 per item
    __shared__ uint4 sd[WPB][GITEMS_];

    const int warp = threadIdx.x >> 5;
    const int lane = threadIdx.x & 31;
    const int g    = blockIdx.x * WPB + warp;      // this warp's group
    const int r0   = g * GR_;

    const bool hasExtra = (lane < GITEMS_ - 32);   // lanes 0..7

    // indices first (coalesced LDGs go in flight immediately)
    const int gb = g * GITEMS_;
    const int i0 = nb[gb + lane];
    const int i1 = hasExtra ? nb[gb + 32 + lane] : 0;

    // per-lane constants (independent loads fill the idx wait)
    // support-paired half2: low = s0/s2, high = s1/s3
    const __half2 D0_01 = u2h(packh2(disp[0*SK_ +  0 + lane], disp[0*SK_ + 32 + lane]));
    const __half2 D0_23 = u2h(packh2(disp[0*SK_ + 64 + lane], disp[0*SK_ + 96 + lane]));
    const __half2 D1_01 = u2h(packh2(disp[1*SK_ +  0 + lane], disp[1*SK_ + 32 + lane]));
    const __half2 D1_23 = u2h(packh2(disp[1*SK_ + 64 + lane], disp[1*SK_ + 96 + lane]));
    const __half2 D2_01 = u2h(packh2(disp[2*SK_ +  0 + lane], disp[2*SK_ + 32 + lane]));
    const __half2 D2_23 = u2h(packh2(disp[2*SK_ + 64 + lane], disp[2*SK_ + 96 + lane]));
    const float w0 = weights[ 0 + lane];
    const float w1 = weights[32 + lane];
    const float w2 = weights[64 + lane];
    const float w3 = weights[96 + lane];

    // batched gather -> fp32 diff -> duplicated half2 in smem
    {
        const int vbase = (r0 >> 13) * (V_ * 3);   // groups never span batches
        const int  row0 = (lane >= N_);            // item = lane
        const float* p0 = verts + vbase + i0 * 3;
        const float* q0 = verts + (r0 + row0) * 3;
        float dx = p0[0]-q0[0], dy = p0[1]-q0[1], dz = p0[2]-q0[2];
        sd[warp][lane] = make_uint4(packh2(dx,dx), packh2(dy,dy),
                                    packh2(dz,dz), 0u);
        if (hasExtra) {                            // item = lane+32 -> row 1
            const float* p1 = verts + vbase + i1 * 3;
            const float* q1 = verts + (r0 + 1) * 3;
            float ex = p1[0]-q1[0], ey = p1[1]-q1[1], ez = p1[2]-q1[2];
            sd[warp][lane + 32] = make_uint4(packh2(ex,ex), packh2(ey,ey),
                                             packh2(ez,ez), 0u);
        }
    }
    __syncwarp();

    // fused 2-row fp16 compute: 4 half2 max chains (8 scalar channels),
    // per j: 2 LDS.128 + 12 HFMA2-class + 4 HMAX2. max seeded 0 == relu.
    const __half2 zero = __float2half2_rn(0.0f);
    __half2 A01 = zero, A23 = zero;     // row 0: (s0,s1) (s2,s3)
    __half2 B01 = zero, B23 = zero;     // row 1
    {
        const uint4* s0 = &sd[warp][0];
        const uint4* s1 = &sd[warp][N_];
        #pragma unroll
        for (int j = 0; j < N_; j++) {
            const uint4 A = s0[j];
            const uint4 B = s1[j];
            const __half2 ax = u2h(A.x), ay = u2h(A.y), az = u2h(A.z);
            const __half2 bx = u2h(B.x), by = u2h(B.y), bz = u2h(B.z);

            __half2 ta01 = __hfma2(ax, D0_01, __hfma2(ay, D1_01, __hmul2(az, D2_01)));
            __half2 tb01 = __hfma2(bx, D0_01, __hfma2(by, D1_01, __hmul2(bz, D2_01)));
            __half2 ta23 = __hfma2(ax, D0_23, __hfma2(ay, D1_23, __hmul2(az, D2_23)));
            __half2 tb23 = __hfma2(bx, D0_23, __hfma2(by, D1_23, __hmul2(bz, D2_23)));

            A01 = __hmax2(A01, ta01);
            B01 = __hmax2(B01, tb01);
            A23 = __hmax2(A23, ta23);
            B23 = __hmax2(B23, tb23);
        }
    }

    // fp32 epilogue: unpack maxes, weight, sum supports
    {
        float m0 = __low2float(A01), m1 = __high2float(A01);
        float m2 = __low2float(A23), m3 = __high2float(A23);
        out[r0 * K_ + lane] =
            fmaf(m0, w0, fmaf(m1, w1, fmaf(m2, w2, m3 * w3)));
        float p0 = __low2float(B01), p1 = __high2float(B01);
        float p2 = __low2float(B23), p3 = __high2float(B23);
        out[(r0 + 1) * K_ + lane] =
            fmaf(p0, w0, fmaf(p1, w1, fmaf(p2, w2, p3 * w3)));
    }
}

extern "C" void kernel_launch(void* const* d_in, const int* in_sizes, int n_in,
                              void* d_out, int out_size)
{
    const int*   nb      = (const int*)  d_in[0];
    const float* verts   = (const float*)d_in[1];
    const float* weights = (const float*)d_in[2];
    const float* disp    = (const float*)d_in[3];
    float*       out     = (float*)      d_out;

    op3d_kernel<<<BLOCKS_, THREADS_>>>(nb, verts, weights, disp, out);
}

// round 16
// speedup vs baseline: 1.4754x; 1.0133x over previous
#include <cuda_runtime.h>
#include <cuda_fp16.h>

// Operator3D: bs=4, v=8192, n=20, SUPPORT=4, KERNEL=32  (S*K = 128)
// inputs: [0] neighbor_index int32 (bs,v,n)
//         [1] vertices       f32   (bs,v,3)
//         [2] weights        f32   (1,1,4,32)
//         [3] displacement   f32   (3,128)
// output: feature f32 (bs,v,32)
//
// One-shot shell (proven R14/R15) + fp16 half2 body (proven R15) + 4-row
// fusion for ILP: the fp16 loop was dependency-bound (issue 52.3%, no pipe
// saturated), so per j we now issue 4 independent LDS.128 + 24 HFMA2 +
// 8 HMAX2 = 36 slots across 16 independent half2 chains -- same chain
// density as the best fp32 body but at half the arithmetic slot cost.
// Gather: 80 items batched over 32 lanes (R6 pattern). One warp = one
// 4-row group, 1024 blocks x 8 warps, no loop, no prefetch state.

#define BS_   4
#define V_    8192
#define N_    20
#define K_    32
#define SK_   128
#define ROWS_ (BS_ * V_)

#define GR_      4
#define GITEMS_  (GR_ * N_)            // 80
#define GROUPS_  (ROWS_ / GR_)         // 8192

#define WPB      8
#define THREADS_ (WPB * 32)
#define BLOCKS_  (GROUPS_ / WPB)       // 1024

typedef unsigned int u32;

__device__ __forceinline__ u32 packh2(float lo, float hi) {  // {low=lo, high=hi}
    u32 r;
    asm("cvt.rn.f16x2.f32 %0, %1, %2;" : "=r"(r) : "f"(hi), "f"(lo));
    return r;
}
__device__ __forceinline__ __half2 u2h(u32 v) {
    __half2 h;
    *reinterpret_cast<u32*>(&h) = v;
    return h;
}

__global__ __launch_bounds__(THREADS_)
void op3d_kernel(const int*   __restrict__ nb,
                 const float* __restrict__ verts,
                 const float* __restrict__ weights,
                 const float* __restrict__ disp,
                 float*       __restrict__ out)
{
    // per item: {(dx,dx),(dy,dy),(dz,dz),pad} as half2 -> one LDS.128 per item
    __shared__ uint4 sd[WPB][GITEMS_];

    const int warp = threadIdx.x >> 5;
    const int lane = threadIdx.x & 31;
    const int g    = blockIdx.x * WPB + warp;      // this warp's group
    const int r0   = g * GR_;

    // indices first: 3 coalesced LDGs in flight immediately (80 items)
    const int gb = g * GITEMS_;
    const int i0 = nb[gb + lane];
    const int i1 = nb[gb + 32 + lane];
    const int i2 = (lane < GITEMS_ - 64) ? nb[gb + 64 + lane] : 0;

    // per-lane constants (independent loads fill the idx wait)
    const __half2 D0_01 = u2h(packh2(disp[0*SK_ +  0 + lane], disp[0*SK_ + 32 + lane]));
    const __half2 D0_23 = u2h(packh2(disp[0*SK_ + 64 + lane], disp[0*SK_ + 96 + lane]));
    const __half2 D1_01 = u2h(packh2(disp[1*SK_ +  0 + lane], disp[1*SK_ + 32 + lane]));
    const __half2 D1_23 = u2h(packh2(disp[1*SK_ + 64 + lane], disp[1*SK_ + 96 + lane]));
    const __half2 D2_01 = u2h(packh2(disp[2*SK_ +  0 + lane], disp[2*SK_ + 32 + lane]));
    const __half2 D2_23 = u2h(packh2(disp[2*SK_ + 64 + lane], disp[2*SK_ + 96 + lane]));
    const float w0 = weights[ 0 + lane];
    const float w1 = weights[32 + lane];
    const float w2 = weights[64 + lane];
    const float w3 = weights[96 + lane];

    // batched gather: item -> row = item/20; fp32 diff -> duplicated half2
    {
        const int vbase = (r0 >> 13) * (V_ * 3);   // groups never span batches
        #define GATHER_(ITEM, IDX) do {                                      \
            const int   _it  = (ITEM);                                       \
            const int   _row = (int)((unsigned)_it / 20u);                   \
            const float* _p  = verts + vbase + (IDX) * 3;                    \
            const float* _q  = verts + (r0 + _row) * 3;                      \
            float _dx = _p[0]-_q[0], _dy = _p[1]-_q[1], _dz = _p[2]-_q[2];   \
            sd[warp][_it] = make_uint4(packh2(_dx,_dx), packh2(_dy,_dy),     \
                                       packh2(_dz,_dz), 0u);                 \
        } while (0)
        GATHER_(lane,      i0);
        GATHER_(lane + 32, i1);
        if (lane < GITEMS_ - 64) GATHER_(lane + 64, i2);
        #undef GATHER_
    }
    __syncwarp();

    // fused 4-row fp16 compute: 8 half2 max chains (16 scalar channels),
    // per j: 4 LDS.128 + 24 HFMA2-class + 8 HMAX2. max seeded 0 == relu.
    const __half2 zero = __float2half2_rn(0.0f);
    __half2 A01 = zero, A23 = zero;     // row 0
    __half2 B01 = zero, B23 = zero;     // row 1
    __half2 C01 = zero, C23 = zero;     // row 2
    __half2 E01 = zero, E23 = zero;     // row 3
    {
        const uint4* s0 = &sd[warp][0];
        const uint4* s1 = &sd[warp][N_];
        const uint4* s2 = &sd[warp][2 * N_];
        const uint4* s3 = &sd[warp][3 * N_];
        #pragma unroll
        for (int j = 0; j < N_; j++) {
            const uint4 A = s0[j];
            const uint4 B = s1[j];
            const uint4 C = s2[j];
            const uint4 E = s3[j];
            const __half2 ax = u2h(A.x), ay = u2h(A.y), az = u2h(A.z);
            const __half2 bx = u2h(B.x), by = u2h(B.y), bz = u2h(B.z);
            const __half2 cx = u2h(C.x), cy = u2h(C.y), cz = u2h(C.z);
            const __half2 ex = u2h(E.x), ey = u2h(E.y), ez = u2h(E.z);

            __half2 ta01 = __hfma2(ax, D0_01, __hfma2(ay, D1_01, __hmul2(az, D2_01)));
            __half2 tb01 = __hfma2(bx, D0_01, __hfma2(by, D1_01, __hmul2(bz, D2_01)));
            __half2 tc01 = __hfma2(cx, D0_01, __hfma2(cy, D1_01, __hmul2(cz, D2_01)));
            __half2 te01 = __hfma2(ex, D0_01, __hfma2(ey, D1_01, __hmul2(ez, D2_01)));
            __half2 ta23 = __hfma2(ax, D0_23, __hfma2(ay, D1_23, __hmul2(az, D2_23)));
            __half2 tb23 = __hfma2(bx, D0_23, __hfma2(by, D1_23, __hmul2(bz, D2_23)));
            __half2 tc23 = __hfma2(cx, D0_23, __hfma2(cy, D1_23, __hmul2(cz, D2_23)));
            __half2 te23 = __hfma2(ex, D0_23, __hfma2(ey, D1_23, __hmul2(ez, D2_23)));

            A01 = __hmax2(A01, ta01);
            B01 = __hmax2(B01, tb01);
            C01 = __hmax2(C01, tc01);
            E01 = __hmax2(E01, te01);
            A23 = __hmax2(A23, ta23);
            B23 = __hmax2(B23, tb23);
            C23 = __hmax2(C23, tc23);
            E23 = __hmax2(E23, te23);
        }
    }

    // fp32 epilogue: unpack maxes, weight, sum supports, store 4 rows
    {
        float m0, m1, m2, m3;
        m0 = __low2float(A01); m1 = __high2float(A01);
        m2 = __low2float(A23); m3 = __high2float(A23);
        out[ r0      * K_ + lane] = fmaf(m0, w0, fmaf(m1, w1, fmaf(m2, w2, m3 * w3)));
        m0 = __low2float(B01); m1 = __high2float(B01);
        m2 = __low2float(B23); m3 = __high2float(B23);
        out[(r0 + 1) * K_ + lane] = fmaf(m0, w0, fmaf(m1, w1, fmaf(m2, w2, m3 * w3)));
        m0 = __low2float(C01); m1 = __high2float(C01);
        m2 = __low2float(C23); m3 = __high2float(C23);
        out[(r0 + 2) * K_ + lane] = fmaf(m0, w0, fmaf(m1, w1, fmaf(m2, w2, m3 * w3)));
        m0 = __low2float(E01); m1 = __high2float(E01);
        m2 = __low2float(E23); m3 = __high2float(E23);
        out[(r0 + 3) * K_ + lane] = fmaf(m0, w0, fmaf(m1, w1, fmaf(m2, w2, m3 * w3)));
    }
}

extern "C" void kernel_launch(void* const* d_in, const int* in_sizes, int n_in,
                              void* d_out, int out_size)
{
    const int*   nb      = (const int*)  d_in[0];
    const float* verts   = (const float*)d_in[1];
    const float* weights = (const float*)d_in[2];
    const float* disp    = (const float*)d_in[3];
    float*       out     = (float*)      d_out;

    op3d_kernel<<<BLOCKS_, THREADS_>>>(nb, verts, weights, disp, out);
}